// round 2
// baseline (speedup 1.0000x reference)
#include <cuda_runtime.h>
#include <cuda_bf16.h>

// Linear-recurrence (blocked scan) formulation of 2M-step RK4 on a 4-state LTI system.
// x_{t+1} = Phi x_t + Gam u_t  (exact algebra of the RK4 step for a linear ODE with
// zero-order-hold input). Three phases:
//   k_pass1  : per-block affine offsets b_p (start from 0)
//   k_combine: two-level scan of block boundary states using Phi^L, Phi^(GSIZE*L)
//   k_pass3  : re-run blocks from correct start states, emit y = (z1, z2) per step.

#define P_BLOCKS 65536
#define NGROUP 256       // groups in combine stage
#define GSIZE 256        // blocks per group; NGROUP*GSIZE == P_BLOCKS

__device__ float g_fPhi[16];
__device__ float g_fGam[8];
__device__ float g_fPhiL[16];
__device__ float g_fPhiLG[16];
__device__ float g_b[P_BLOCKS * 4];
__device__ float g_xs[P_BLOCKS * 4];

__device__ __forceinline__ void mm4(const double* A, const double* B, double* C) {
    for (int i = 0; i < 4; i++)
        for (int j = 0; j < 4; j++) {
            double s = 0.0;
            for (int kk = 0; kk < 4; kk++) s += A[i * 4 + kk] * B[kk * 4 + j];
            C[i * 4 + j] = s;
        }
}

__global__ void k_init(const float* c, const float* m, const float* k,
                       const float* dtp, int L) {
    // single thread: build Phi, Gam, Phi^L, Phi^(L*GSIZE) in double, store float copies
    double c1 = c[0], c2 = c[1], c3 = c[2];
    double m1 = m[0], m2 = m[1];
    double k1 = k[0], k2 = k[1], k3 = k[2];
    double h = dtp[0];

    double A[16] = {
        0.0, 1.0, 0.0, 0.0,
        -(k1 + k2) / m1, -(c1 + c2) / m1, k2 / m1, c2 / m1,
        0.0, 0.0, 0.0, 1.0,
        k2 / m2, c2 / m2, -(k3 + k2) / m2, -(c3 + c2) / m2
    };
    double A2[16], A3[16], A4[16];
    mm4(A, A, A2); mm4(A2, A, A3); mm4(A3, A, A4);

    double Phi[16], G4[16];
    double h2 = h * h, h3 = h2 * h, h4 = h3 * h;
    for (int i = 0; i < 16; i++) {
        double id = (i % 5 == 0) ? 1.0 : 0.0;
        Phi[i] = id + h * A[i] + (h2 / 2.0) * A2[i] + (h3 / 6.0) * A3[i] + (h4 / 24.0) * A4[i];
        G4[i]  = h * id + (h2 / 2.0) * A[i] + (h3 / 6.0) * A2[i] + (h4 / 24.0) * A3[i];
    }
    for (int i = 0; i < 16; i++) g_fPhi[i] = (float)Phi[i];
    // Gam = G4 * B,   B[1][0] = 1/m1, B[3][1] = 1/m2
    for (int r = 0; r < 4; r++) {
        g_fGam[r * 2 + 0] = (float)(G4[r * 4 + 1] / m1);
        g_fGam[r * 2 + 1] = (float)(G4[r * 4 + 3] / m2);
    }
    // PhiL = Phi^L (binary exponentiation in double)
    double R[16], Bs[16], Tm[16];
    for (int i = 0; i < 16; i++) { R[i] = (i % 5 == 0) ? 1.0 : 0.0; Bs[i] = Phi[i]; }
    int e = L;
    while (e) {
        if (e & 1) { mm4(R, Bs, Tm); for (int i = 0; i < 16; i++) R[i] = Tm[i]; }
        e >>= 1;
        if (e) { mm4(Bs, Bs, Tm); for (int i = 0; i < 16; i++) Bs[i] = Tm[i]; }
    }
    for (int i = 0; i < 16; i++) g_fPhiL[i] = (float)R[i];
    // PhiLG = PhiL^GSIZE  (GSIZE = 256 = 2^8 -> 8 squarings)
    for (int s = 0; s < 8; s++) { mm4(R, R, Tm); for (int i = 0; i < 16; i++) R[i] = Tm[i]; }
    for (int i = 0; i < 16; i++) g_fPhiLG[i] = (float)R[i];
}

#define STEP(ua, ub)                                                                         \
    do {                                                                                     \
        float n0 = fmaf(P[3],  x3, fmaf(P[2],  x2, fmaf(P[1],  x1, fmaf(P[0],  x0,          \
                   fmaf(G[1], (ub), G[0] * (ua))))));                                        \
        float n1 = fmaf(P[7],  x3, fmaf(P[6],  x2, fmaf(P[5],  x1, fmaf(P[4],  x0,          \
                   fmaf(G[3], (ub), G[2] * (ua))))));                                        \
        float n2 = fmaf(P[11], x3, fmaf(P[10], x2, fmaf(P[9],  x1, fmaf(P[8],  x0,          \
                   fmaf(G[5], (ub), G[4] * (ua))))));                                        \
        float n3 = fmaf(P[15], x3, fmaf(P[14], x2, fmaf(P[13], x1, fmaf(P[12], x0,          \
                   fmaf(G[7], (ub), G[6] * (ua))))));                                        \
        x0 = n0; x1 = n1; x2 = n2; x3 = n3;                                                  \
    } while (0)

__global__ void __launch_bounds__(256) k_pass1(const float* __restrict__ u, int T, int L) {
    int p = blockIdx.x * blockDim.x + threadIdx.x;
    float P[16], G[8];
#pragma unroll
    for (int i = 0; i < 16; i++) P[i] = g_fPhi[i];
#pragma unroll
    for (int i = 0; i < 8; i++) G[i] = g_fGam[i];

    float x0 = 0.f, x1 = 0.f, x2 = 0.f, x3 = 0.f;
    int t0 = p * L;
    int te = t0 + L; if (te > T) te = T;
    int t = t0;
    for (; t + 2 <= te; t += 2) {
        float4 uu = *(const float4*)(u + 2 * t);   // L even -> 16B aligned
        STEP(uu.x, uu.y);
        STEP(uu.z, uu.w);
    }
    if (t < te) {
        float2 uu = *(const float2*)(u + 2 * t);
        STEP(uu.x, uu.y);
    }
    g_b[p * 4 + 0] = x0; g_b[p * 4 + 1] = x1;
    g_b[p * 4 + 2] = x2; g_b[p * 4 + 3] = x3;
}

__global__ void k_combine(const float* __restrict__ x0in) {
    __shared__ float S[NGROUP][4];
    __shared__ float XG[NGROUP][4];
    int s = threadIdx.x;
    float M[16];
#pragma unroll
    for (int i = 0; i < 16; i++) M[i] = g_fPhiL[i];

    // stage 1: per-group offset (start from 0)
    float y0 = 0.f, y1 = 0.f, y2 = 0.f, y3 = 0.f;
    for (int i = 0; i < GSIZE; i++) {
        int p = s * GSIZE + i;
        float b0 = g_b[p * 4 + 0], b1 = g_b[p * 4 + 1];
        float b2 = g_b[p * 4 + 2], b3 = g_b[p * 4 + 3];
        float n0 = fmaf(M[0],  y0, fmaf(M[1],  y1, fmaf(M[2],  y2, fmaf(M[3],  y3, b0))));
        float n1 = fmaf(M[4],  y0, fmaf(M[5],  y1, fmaf(M[6],  y2, fmaf(M[7],  y3, b1))));
        float n2 = fmaf(M[8],  y0, fmaf(M[9],  y1, fmaf(M[10], y2, fmaf(M[11], y3, b2))));
        float n3 = fmaf(M[12], y0, fmaf(M[13], y1, fmaf(M[14], y2, fmaf(M[15], y3, b3))));
        y0 = n0; y1 = n1; y2 = n2; y3 = n3;
    }
    S[s][0] = y0; S[s][1] = y1; S[s][2] = y2; S[s][3] = y3;
    __syncthreads();

    // stage 2: serial scan over the NGROUP group boundaries
    if (s == 0) {
        float MG[16];
#pragma unroll
        for (int i = 0; i < 16; i++) MG[i] = g_fPhiLG[i];
        float z0 = x0in[0], z1 = x0in[1], z2 = x0in[2], z3 = x0in[3];
        for (int q = 0; q < NGROUP; q++) {
            XG[q][0] = z0; XG[q][1] = z1; XG[q][2] = z2; XG[q][3] = z3;
            float n0 = fmaf(MG[0],  z0, fmaf(MG[1],  z1, fmaf(MG[2],  z2, fmaf(MG[3],  z3, S[q][0]))));
            float n1 = fmaf(MG[4],  z0, fmaf(MG[5],  z1, fmaf(MG[6],  z2, fmaf(MG[7],  z3, S[q][1]))));
            float n2 = fmaf(MG[8],  z0, fmaf(MG[9],  z1, fmaf(MG[10], z2, fmaf(MG[11], z3, S[q][2]))));
            float n3 = fmaf(MG[12], z0, fmaf(MG[13], z1, fmaf(MG[14], z2, fmaf(MG[15], z3, S[q][3]))));
            z0 = n0; z1 = n1; z2 = n2; z3 = n3;
        }
    }
    __syncthreads();

    // stage 3: per-block start states within each group
    y0 = XG[s][0]; y1 = XG[s][1]; y2 = XG[s][2]; y3 = XG[s][3];
    for (int i = 0; i < GSIZE; i++) {
        int p = s * GSIZE + i;
        g_xs[p * 4 + 0] = y0; g_xs[p * 4 + 1] = y1;
        g_xs[p * 4 + 2] = y2; g_xs[p * 4 + 3] = y3;
        float b0 = g_b[p * 4 + 0], b1 = g_b[p * 4 + 1];
        float b2 = g_b[p * 4 + 2], b3 = g_b[p * 4 + 3];
        float n0 = fmaf(M[0],  y0, fmaf(M[1],  y1, fmaf(M[2],  y2, fmaf(M[3],  y3, b0))));
        float n1 = fmaf(M[4],  y0, fmaf(M[5],  y1, fmaf(M[6],  y2, fmaf(M[7],  y3, b1))));
        float n2 = fmaf(M[8],  y0, fmaf(M[9],  y1, fmaf(M[10], y2, fmaf(M[11], y3, b2))));
        float n3 = fmaf(M[12], y0, fmaf(M[13], y1, fmaf(M[14], y2, fmaf(M[15], y3, b3))));
        y0 = n0; y1 = n1; y2 = n2; y3 = n3;
    }
}

__global__ void __launch_bounds__(256) k_pass3(const float* __restrict__ u,
                                               float* __restrict__ out, int T, int L) {
    int p = blockIdx.x * blockDim.x + threadIdx.x;
    int t0 = p * L;
    if (t0 >= T) return;
    float P[16], G[8];
#pragma unroll
    for (int i = 0; i < 16; i++) P[i] = g_fPhi[i];
#pragma unroll
    for (int i = 0; i < 8; i++) G[i] = g_fGam[i];

    float x0 = g_xs[p * 4 + 0], x1 = g_xs[p * 4 + 1];
    float x2 = g_xs[p * 4 + 2], x3 = g_xs[p * 4 + 3];
    int te = t0 + L; if (te > T) te = T;
    int t = t0;
    for (; t + 2 <= te; t += 2) {
        float4 uu = *(const float4*)(u + 2 * t);
        STEP(uu.x, uu.y);
        float o0 = x0, o1 = x2;
        STEP(uu.z, uu.w);
        *(float4*)(out + 2 * t) = make_float4(o0, o1, x0, x2);
    }
    if (t < te) {
        float2 uu = *(const float2*)(u + 2 * t);
        STEP(uu.x, uu.y);
        *(float2*)(out + 2 * t) = make_float2(x0, x2);
    }
}

extern "C" void kernel_launch(void* const* d_in, const int* in_sizes, int n_in,
                              void* d_out, int out_size) {
    const float* u  = (const float*)d_in[0];
    const float* x0 = (const float*)d_in[1];
    const float* c  = (const float*)d_in[2];
    const float* m  = (const float*)d_in[3];
    const float* k  = (const float*)d_in[4];
    const float* dt = (const float*)d_in[5];
    float* out = (float*)d_out;

    int T = in_sizes[0] / 2;
    int L = (T + P_BLOCKS - 1) / P_BLOCKS;
    L = (L + 1) & ~1;   // even -> float4 alignment of per-thread u chunks

    k_init<<<1, 1>>>(c, m, k, dt, L);
    k_pass1<<<P_BLOCKS / 256, 256>>>(u, T, L);
    k_combine<<<1, NGROUP>>>(x0);
    k_pass3<<<P_BLOCKS / 256, 256>>>(u, out, T, L);
}

// round 3
// speedup vs baseline: 4.5103x; 4.5103x over previous
#include <cuda_runtime.h>
#include <cuda_bf16.h>

// Blocked-scan formulation of 2M-step RK4 on a 4-state LTI system.
// x_{t+1} = Phi x_t + Gam u_t (exact RK4 algebra for linear ODE + ZOH input).
//   k_init   : 16-thread double-precision build of Phi, Gam, Phi^L, Phi^(GSIZE*L)
//   k_pass1  : per-chain affine offsets b_p (start from 0); stores TRANSPOSED
//   k_combine: two-level scan, fully coalesced thanks to transposed layout
//   k_pass3  : re-run chains from correct starts, emit y = (z1, z2).

#define P_BLOCKS 65536
#define NGROUP 256       // groups in combine stage
#define GSIZE 256        // chains per group; NGROUP*GSIZE == P_BLOCKS

__device__ float g_fPhi[16];
__device__ float g_fGam[8];
__device__ float g_fPhiL[16];
__device__ float g_fPhiLG[16];
// transposed planes: element [i][s] = chain p = s*GSIZE + i   (i = pos in group, s = group)
__device__ float4 g_b[P_BLOCKS];
__device__ float4 g_xs[P_BLOCKS];

__global__ void k_init(const float* c, const float* m, const float* k,
                       const float* dtp, int L) {
    __shared__ double sA[16], sP[16], sT[16], sR[16], sBs[16];
    int t = threadIdx.x;           // 16 threads
    int r = t >> 2, col = t & 3;

    double c1 = c[0], c2 = c[1], c3 = c[2];
    double m1 = m[0], m2 = m[1];
    double k1 = k[0], k2 = k[1], k3 = k[2];
    double h = dtp[0];

    if (t == 0) {
        sA[0] = 0.0;  sA[1] = 1.0;  sA[2] = 0.0;  sA[3] = 0.0;
        sA[4] = -(k1 + k2) / m1; sA[5] = -(c1 + c2) / m1; sA[6] = k2 / m1; sA[7] = c2 / m1;
        sA[8] = 0.0;  sA[9] = 0.0;  sA[10] = 0.0; sA[11] = 1.0;
        sA[12] = k2 / m2; sA[13] = c2 / m2; sA[14] = -(k3 + k2) / m2; sA[15] = -(c3 + c2) / m2;
    }
    __syncwarp(0xffffu);

    double id = (r == col) ? 1.0 : 0.0;
    double h2 = h * h, h3 = h2 * h, h4 = h3 * h;
    double ph = id + h * sA[t];                 // Phi accumulator
    double g4 = h * id + (h2 / 2.0) * sA[t];    // G4 accumulator
    sP[t] = sA[t];
    __syncwarp(0xffffu);

    double coefP[3] = { h2 / 2.0, h3 / 6.0, h4 / 24.0 };
    double coefG[2] = { h3 / 6.0, h4 / 24.0 };
    for (int q = 0; q < 3; q++) {               // A^2, A^3, A^4
        double s = 0.0;
        for (int kk = 0; kk < 4; kk++) s += sP[r * 4 + kk] * sA[kk * 4 + col];
        __syncwarp(0xffffu);
        sP[t] = s;
        __syncwarp(0xffffu);
        ph += coefP[q] * s;
        if (q < 2) g4 += coefG[q] * s;
    }

    g_fPhi[t] = (float)ph;
    sT[t] = g4;
    __syncwarp(0xffffu);
    if (t < 8) {   // Gam = G4 * B with B[1][0]=1/m1, B[3][1]=1/m2
        int rr = t >> 1, cc = t & 1;
        g_fGam[t] = (float)(sT[rr * 4 + (cc ? 3 : 1)] / (cc ? m2 : m1));
    }

    // PhiL = Phi^L (binary exponentiation, parallel 4x4 matmuls)
    sR[t] = id;
    sBs[t] = ph;
    __syncwarp(0xffffu);
    int e = L;
    while (e) {
        if (e & 1) {
            double s = 0.0;
            for (int kk = 0; kk < 4; kk++) s += sR[r * 4 + kk] * sBs[kk * 4 + col];
            __syncwarp(0xffffu);
            sR[t] = s;
            __syncwarp(0xffffu);
        }
        e >>= 1;
        if (e) {
            double s = 0.0;
            for (int kk = 0; kk < 4; kk++) s += sBs[r * 4 + kk] * sBs[kk * 4 + col];
            __syncwarp(0xffffu);
            sBs[t] = s;
            __syncwarp(0xffffu);
        }
    }
    g_fPhiL[t] = (float)sR[t];
    // PhiLG = PhiL^GSIZE (GSIZE = 256 -> 8 squarings)
    for (int q = 0; q < 8; q++) {
        double s = 0.0;
        for (int kk = 0; kk < 4; kk++) s += sR[r * 4 + kk] * sR[kk * 4 + col];
        __syncwarp(0xffffu);
        sR[t] = s;
        __syncwarp(0xffffu);
    }
    g_fPhiLG[t] = (float)sR[t];
}

#define STEP(ua, ub)                                                                         \
    do {                                                                                     \
        float n0 = fmaf(P[3],  x3, fmaf(P[2],  x2, fmaf(P[1],  x1, fmaf(P[0],  x0,          \
                   fmaf(G[1], (ub), G[0] * (ua))))));                                        \
        float n1 = fmaf(P[7],  x3, fmaf(P[6],  x2, fmaf(P[5],  x1, fmaf(P[4],  x0,          \
                   fmaf(G[3], (ub), G[2] * (ua))))));                                        \
        float n2 = fmaf(P[11], x3, fmaf(P[10], x2, fmaf(P[9],  x1, fmaf(P[8],  x0,          \
                   fmaf(G[5], (ub), G[4] * (ua))))));                                        \
        float n3 = fmaf(P[15], x3, fmaf(P[14], x2, fmaf(P[13], x1, fmaf(P[12], x0,          \
                   fmaf(G[7], (ub), G[6] * (ua))))));                                        \
        x0 = n0; x1 = n1; x2 = n2; x3 = n3;                                                  \
    } while (0)

#define MATVEC(M, y0, y1, y2, y3, b0, b1, b2, b3)                                            \
    do {                                                                                     \
        float n0 = fmaf(M[0],  y0, fmaf(M[1],  y1, fmaf(M[2],  y2, fmaf(M[3],  y3, b0))));   \
        float n1 = fmaf(M[4],  y0, fmaf(M[5],  y1, fmaf(M[6],  y2, fmaf(M[7],  y3, b1))));   \
        float n2 = fmaf(M[8],  y0, fmaf(M[9],  y1, fmaf(M[10], y2, fmaf(M[11], y3, b2))));   \
        float n3 = fmaf(M[12], y0, fmaf(M[13], y1, fmaf(M[14], y2, fmaf(M[15], y3, b3))));   \
        y0 = n0; y1 = n1; y2 = n2; y3 = n3;                                                  \
    } while (0)

__global__ void __launch_bounds__(256) k_pass1(const float* __restrict__ u, int T, int L) {
    int p = blockIdx.x * blockDim.x + threadIdx.x;
    float P[16], G[8];
#pragma unroll
    for (int i = 0; i < 16; i++) P[i] = g_fPhi[i];
#pragma unroll
    for (int i = 0; i < 8; i++) G[i] = g_fGam[i];

    float x0 = 0.f, x1 = 0.f, x2 = 0.f, x3 = 0.f;
    int t0 = p * L;
    int te = t0 + L; if (te > T) te = T;
    int t = t0;
    for (; t + 2 <= te; t += 2) {
        float4 uu = *(const float4*)(u + 2 * t);   // L even -> 16B aligned
        STEP(uu.x, uu.y);
        STEP(uu.z, uu.w);
    }
    if (t < te) {
        float2 uu = *(const float2*)(u + 2 * t);
        STEP(uu.x, uu.y);
    }
    // transposed store: [i][s] with i = p % GSIZE, s = p / GSIZE
    g_b[(p & (GSIZE - 1)) * NGROUP + (p >> 8)] = make_float4(x0, x1, x2, x3);
}

__global__ void k_combine(const float* __restrict__ x0in) {
    __shared__ float S[NGROUP][4];
    __shared__ float XG[NGROUP][4];
    int s = threadIdx.x;
    float M[16];
#pragma unroll
    for (int i = 0; i < 16; i++) M[i] = g_fPhiL[i];

    // stage 1: per-group offset (start from 0); coalesced loads
    float y0 = 0.f, y1 = 0.f, y2 = 0.f, y3 = 0.f;
    for (int i = 0; i < GSIZE; i++) {
        float4 b = g_b[i * NGROUP + s];
        MATVEC(M, y0, y1, y2, y3, b.x, b.y, b.z, b.w);
    }
    S[s][0] = y0; S[s][1] = y1; S[s][2] = y2; S[s][3] = y3;
    __syncthreads();

    // stage 2: serial scan over the NGROUP group boundaries
    if (s == 0) {
        float MG[16];
#pragma unroll
        for (int i = 0; i < 16; i++) MG[i] = g_fPhiLG[i];
        float z0 = x0in[0], z1 = x0in[1], z2 = x0in[2], z3 = x0in[3];
        for (int q = 0; q < NGROUP; q++) {
            XG[q][0] = z0; XG[q][1] = z1; XG[q][2] = z2; XG[q][3] = z3;
            MATVEC(MG, z0, z1, z2, z3, S[q][0], S[q][1], S[q][2], S[q][3]);
        }
    }
    __syncthreads();

    // stage 3: per-chain start states; coalesced stores + loads
    y0 = XG[s][0]; y1 = XG[s][1]; y2 = XG[s][2]; y3 = XG[s][3];
    for (int i = 0; i < GSIZE; i++) {
        g_xs[i * NGROUP + s] = make_float4(y0, y1, y2, y3);
        float4 b = g_b[i * NGROUP + s];
        MATVEC(M, y0, y1, y2, y3, b.x, b.y, b.z, b.w);
    }
}

__global__ void __launch_bounds__(256) k_pass3(const float* __restrict__ u,
                                               float* __restrict__ out, int T, int L) {
    int p = blockIdx.x * blockDim.x + threadIdx.x;
    int t0 = p * L;
    if (t0 >= T) return;
    float P[16], G[8];
#pragma unroll
    for (int i = 0; i < 16; i++) P[i] = g_fPhi[i];
#pragma unroll
    for (int i = 0; i < 8; i++) G[i] = g_fGam[i];

    float4 xs = g_xs[(p & (GSIZE - 1)) * NGROUP + (p >> 8)];
    float x0 = xs.x, x1 = xs.y, x2 = xs.z, x3 = xs.w;
    int te = t0 + L; if (te > T) te = T;
    int t = t0;
    for (; t + 2 <= te; t += 2) {
        float4 uu = *(const float4*)(u + 2 * t);
        STEP(uu.x, uu.y);
        float o0 = x0, o1 = x2;
        STEP(uu.z, uu.w);
        *(float4*)(out + 2 * t) = make_float4(o0, o1, x0, x2);
    }
    if (t < te) {
        float2 uu = *(const float2*)(u + 2 * t);
        STEP(uu.x, uu.y);
        *(float2*)(out + 2 * t) = make_float2(x0, x2);
    }
}

extern "C" void kernel_launch(void* const* d_in, const int* in_sizes, int n_in,
                              void* d_out, int out_size) {
    const float* u  = (const float*)d_in[0];
    const float* x0 = (const float*)d_in[1];
    const float* c  = (const float*)d_in[2];
    const float* m  = (const float*)d_in[3];
    const float* k  = (const float*)d_in[4];
    const float* dt = (const float*)d_in[5];
    float* out = (float*)d_out;

    int T = in_sizes[0] / 2;
    int L = (T + P_BLOCKS - 1) / P_BLOCKS;
    L = (L + 1) & ~1;   // even -> float4 alignment of per-thread u chunks

    k_init<<<1, 16>>>(c, m, k, dt, L);
    k_pass1<<<P_BLOCKS / 256, 256>>>(u, T, L);
    k_combine<<<1, NGROUP>>>(x0);
    k_pass3<<<P_BLOCKS / 256, 256>>>(u, out, T, L);
}

// round 4
// speedup vs baseline: 4.8803x; 1.0820x over previous
#include <cuda_runtime.h>
#include <cuda_bf16.h>

// Blocked-scan formulation of 2M-step RK4 on a 4-state LTI system.
// x_{t+1} = Phi x_t + Gam u_t (exact RK4 algebra for linear ODE + ZOH input).
//   k_init   : 16-thread double build of Phi, Gam, Phi^L, M_s = Phi^(128L*2^s) s=0..9
//   k_pass1  : per-chain affine offsets b_p (from 0); transposed coalesced store
//   k_combine: 1024 threads; serial 128-chain group scans + Kogge-Stone over groups
//   k_pass3  : re-run chains from correct starts, emit y = (z1, z2).

#define P_CHAINS 131072
#define CB_THREADS 1024
#define CPG 128          // chains per combine thread; CB_THREADS*CPG == P_CHAINS

__device__ float g_fPhi[16];
__device__ float g_fGam[8];
__device__ float g_fPhiL[16];
__device__ float g_fM[10][16];       // M_s = Phi^(CPG*L*2^s)
__device__ float4 g_b[P_CHAINS];     // [i][g]: chain p = g*CPG + i  at  i*CB_THREADS + g
__device__ float4 g_xs[P_CHAINS];

__global__ void k_init(const float* c, const float* m, const float* k,
                       const float* dtp, int L) {
    __shared__ double sA[16], sP[16], sT[16], sR[16], sBs[16];
    int t = threadIdx.x;           // 16 threads
    int r = t >> 2, col = t & 3;

    double c1 = c[0], c2 = c[1], c3 = c[2];
    double m1 = m[0], m2 = m[1];
    double k1 = k[0], k2 = k[1], k3 = k[2];
    double h = dtp[0];

    if (t == 0) {
        sA[0] = 0.0;  sA[1] = 1.0;  sA[2] = 0.0;  sA[3] = 0.0;
        sA[4] = -(k1 + k2) / m1; sA[5] = -(c1 + c2) / m1; sA[6] = k2 / m1; sA[7] = c2 / m1;
        sA[8] = 0.0;  sA[9] = 0.0;  sA[10] = 0.0; sA[11] = 1.0;
        sA[12] = k2 / m2; sA[13] = c2 / m2; sA[14] = -(k3 + k2) / m2; sA[15] = -(c3 + c2) / m2;
    }
    __syncwarp(0xffffu);

    double id = (r == col) ? 1.0 : 0.0;
    double h2 = h * h, h3 = h2 * h, h4 = h3 * h;
    double ph = id + h * sA[t];                 // Phi accumulator
    double g4 = h * id + (h2 / 2.0) * sA[t];    // G4 accumulator
    sP[t] = sA[t];
    __syncwarp(0xffffu);

    double coefP[3] = { h2 / 2.0, h3 / 6.0, h4 / 24.0 };
    double coefG[2] = { h3 / 6.0, h4 / 24.0 };
    for (int q = 0; q < 3; q++) {               // A^2, A^3, A^4
        double s = 0.0;
        for (int kk = 0; kk < 4; kk++) s += sP[r * 4 + kk] * sA[kk * 4 + col];
        __syncwarp(0xffffu);
        sP[t] = s;
        __syncwarp(0xffffu);
        ph += coefP[q] * s;
        if (q < 2) g4 += coefG[q] * s;
    }

    g_fPhi[t] = (float)ph;
    sT[t] = g4;
    __syncwarp(0xffffu);
    if (t < 8) {   // Gam = G4 * B with B[1][0]=1/m1, B[3][1]=1/m2
        int rr = t >> 1, cc = t & 1;
        g_fGam[t] = (float)(sT[rr * 4 + (cc ? 3 : 1)] / (cc ? m2 : m1));
    }

    // PhiL = Phi^L (binary exponentiation, parallel 4x4 matmuls)
    sR[t] = id;
    sBs[t] = ph;
    __syncwarp(0xffffu);
    int e = L;
    while (e) {
        if (e & 1) {
            double s = 0.0;
            for (int kk = 0; kk < 4; kk++) s += sR[r * 4 + kk] * sBs[kk * 4 + col];
            __syncwarp(0xffffu);
            sR[t] = s;
            __syncwarp(0xffffu);
        }
        e >>= 1;
        if (e) {
            double s = 0.0;
            for (int kk = 0; kk < 4; kk++) s += sBs[r * 4 + kk] * sBs[kk * 4 + col];
            __syncwarp(0xffffu);
            sBs[t] = s;
            __syncwarp(0xffffu);
        }
    }
    g_fPhiL[t] = (float)sR[t];

    // M0 = PhiL^CPG (CPG=128 -> 7 squarings), then M_{s+1} = M_s^2
    for (int q = 0; q < 7; q++) {
        double s = 0.0;
        for (int kk = 0; kk < 4; kk++) s += sR[r * 4 + kk] * sR[kk * 4 + col];
        __syncwarp(0xffffu);
        sR[t] = s;
        __syncwarp(0xffffu);
    }
    g_fM[0][t] = (float)sR[t];
    for (int ms = 1; ms < 10; ms++) {
        double s = 0.0;
        for (int kk = 0; kk < 4; kk++) s += sR[r * 4 + kk] * sR[kk * 4 + col];
        __syncwarp(0xffffu);
        sR[t] = s;
        __syncwarp(0xffffu);
        g_fM[ms][t] = (float)sR[t];
    }
}

#define STEP(ua, ub)                                                                         \
    do {                                                                                     \
        float n0 = fmaf(P[3],  x3, fmaf(P[2],  x2, fmaf(P[1],  x1, fmaf(P[0],  x0,          \
                   fmaf(G[1], (ub), G[0] * (ua))))));                                        \
        float n1 = fmaf(P[7],  x3, fmaf(P[6],  x2, fmaf(P[5],  x1, fmaf(P[4],  x0,          \
                   fmaf(G[3], (ub), G[2] * (ua))))));                                        \
        float n2 = fmaf(P[11], x3, fmaf(P[10], x2, fmaf(P[9],  x1, fmaf(P[8],  x0,          \
                   fmaf(G[5], (ub), G[4] * (ua))))));                                        \
        float n3 = fmaf(P[15], x3, fmaf(P[14], x2, fmaf(P[13], x1, fmaf(P[12], x0,          \
                   fmaf(G[7], (ub), G[6] * (ua))))));                                        \
        x0 = n0; x1 = n1; x2 = n2; x3 = n3;                                                  \
    } while (0)

#define MATVEC(M, y0, y1, y2, y3, b0, b1, b2, b3)                                            \
    do {                                                                                     \
        float n0 = fmaf(M[0],  y0, fmaf(M[1],  y1, fmaf(M[2],  y2, fmaf(M[3],  y3, b0))));   \
        float n1 = fmaf(M[4],  y0, fmaf(M[5],  y1, fmaf(M[6],  y2, fmaf(M[7],  y3, b1))));   \
        float n2 = fmaf(M[8],  y0, fmaf(M[9],  y1, fmaf(M[10], y2, fmaf(M[11], y3, b2))));   \
        float n3 = fmaf(M[12], y0, fmaf(M[13], y1, fmaf(M[14], y2, fmaf(M[15], y3, b3))));   \
        y0 = n0; y1 = n1; y2 = n2; y3 = n3;                                                  \
    } while (0)

__global__ void __launch_bounds__(256) k_pass1(const float* __restrict__ u, int T, int L) {
    int p = blockIdx.x * blockDim.x + threadIdx.x;
    float P[16], G[8];
#pragma unroll
    for (int i = 0; i < 16; i++) P[i] = g_fPhi[i];
#pragma unroll
    for (int i = 0; i < 8; i++) G[i] = g_fGam[i];

    float x0 = 0.f, x1 = 0.f, x2 = 0.f, x3 = 0.f;
    int t0 = p * L;
    int te = t0 + L; if (te > T) te = T;
    int t = t0;
    // 8-step chunks: 4 front-batched float4 loads (MLP 4)
    for (; t + 8 <= te; t += 8) {
        const float4* b4 = (const float4*)(u + 2 * t);
        float4 a0 = b4[0], a1 = b4[1], a2 = b4[2], a3 = b4[3];
        STEP(a0.x, a0.y); STEP(a0.z, a0.w);
        STEP(a1.x, a1.y); STEP(a1.z, a1.w);
        STEP(a2.x, a2.y); STEP(a2.z, a2.w);
        STEP(a3.x, a3.y); STEP(a3.z, a3.w);
    }
    for (; t + 2 <= te; t += 2) {
        float4 a = *(const float4*)(u + 2 * t);
        STEP(a.x, a.y); STEP(a.z, a.w);
    }
    if (t < te) {
        float2 a = *(const float2*)(u + 2 * t);
        STEP(a.x, a.y);
    }
    // transposed store: [i][g] with i = p % CPG, g = p / CPG
    g_b[(p & (CPG - 1)) * CB_THREADS + (p >> 7)] = make_float4(x0, x1, x2, x3);
}

__global__ void __launch_bounds__(CB_THREADS) k_combine(const float* __restrict__ x0in) {
    __shared__ float sM[10][16];
    __shared__ float4 V[CB_THREADS];
    int g = threadIdx.x;
    if (g < 160) ((float*)sM)[g] = ((const float*)g_fM)[g];

    float Mf[16];
#pragma unroll
    for (int i = 0; i < 16; i++) Mf[i] = g_fPhiL[i];

    // stage 1: serial scan of this thread's CPG chains; thread 0 starts from x0
    float y0 = 0.f, y1 = 0.f, y2 = 0.f, y3 = 0.f;
    if (g == 0) { y0 = x0in[0]; y1 = x0in[1]; y2 = x0in[2]; y3 = x0in[3]; }
#pragma unroll 4
    for (int i = 0; i < CPG; i++) {
        float4 b = g_b[i * CB_THREADS + g];
        MATVEC(Mf, y0, y1, y2, y3, b.x, b.y, b.z, b.w);
    }
    V[g] = make_float4(y0, y1, y2, y3);
    __syncthreads();

    // stage 2: Kogge-Stone inclusive scan over group aggregates.
    // step s: v_g += M_s * v_{g-2^s}, M_s = Phi^(CPG*L*2^s) (shared by all lanes)
#pragma unroll
    for (int s = 0; s < 10; s++) {
        int d = 1 << s;
        float4 w = make_float4(0.f, 0.f, 0.f, 0.f);
        if (g >= d) w = V[g - d];
        __syncthreads();
        if (g >= d) {
            const float* M = sM[s];
            y0 = fmaf(M[0],  w.x, fmaf(M[1],  w.y, fmaf(M[2],  w.z, fmaf(M[3],  w.w, y0))));
            y1 = fmaf(M[4],  w.x, fmaf(M[5],  w.y, fmaf(M[6],  w.z, fmaf(M[7],  w.w, y1))));
            y2 = fmaf(M[8],  w.x, fmaf(M[9],  w.y, fmaf(M[10], w.z, fmaf(M[11], w.w, y2))));
            y3 = fmaf(M[12], w.x, fmaf(M[13], w.y, fmaf(M[14], w.z, fmaf(M[15], w.w, y3))));
            V[g] = make_float4(y0, y1, y2, y3);
        }
        __syncthreads();
    }

    // stage 3: exclusive start per group, then serial starts per chain
    float4 st;
    if (g == 0) st = make_float4(x0in[0], x0in[1], x0in[2], x0in[3]);
    else        st = V[g - 1];
    y0 = st.x; y1 = st.y; y2 = st.z; y3 = st.w;
#pragma unroll 4
    for (int i = 0; i < CPG; i++) {
        g_xs[i * CB_THREADS + g] = make_float4(y0, y1, y2, y3);
        float4 b = g_b[i * CB_THREADS + g];
        MATVEC(Mf, y0, y1, y2, y3, b.x, b.y, b.z, b.w);
    }
}

__global__ void __launch_bounds__(256) k_pass3(const float* __restrict__ u,
                                               float* __restrict__ out, int T, int L) {
    int p = blockIdx.x * blockDim.x + threadIdx.x;
    int t0 = p * L;
    if (t0 >= T) return;
    float P[16], G[8];
#pragma unroll
    for (int i = 0; i < 16; i++) P[i] = g_fPhi[i];
#pragma unroll
    for (int i = 0; i < 8; i++) G[i] = g_fGam[i];

    float4 xs = g_xs[(p & (CPG - 1)) * CB_THREADS + (p >> 7)];
    float x0 = xs.x, x1 = xs.y, x2 = xs.z, x3 = xs.w;
    int te = t0 + L; if (te > T) te = T;
    int t = t0;
    for (; t + 8 <= te; t += 8) {
        const float4* b4 = (const float4*)(u + 2 * t);
        float4 a0 = b4[0], a1 = b4[1], a2 = b4[2], a3 = b4[3];
        float4* o4 = (float4*)(out + 2 * t);
        STEP(a0.x, a0.y); float p0 = x0, q0 = x2;
        STEP(a0.z, a0.w); o4[0] = make_float4(p0, q0, x0, x2);
        STEP(a1.x, a1.y); float p1 = x0, q1 = x2;
        STEP(a1.z, a1.w); o4[1] = make_float4(p1, q1, x0, x2);
        STEP(a2.x, a2.y); float p2 = x0, q2 = x2;
        STEP(a2.z, a2.w); o4[2] = make_float4(p2, q2, x0, x2);
        STEP(a3.x, a3.y); float p3 = x0, q3 = x2;
        STEP(a3.z, a3.w); o4[3] = make_float4(p3, q3, x0, x2);
    }
    for (; t + 2 <= te; t += 2) {
        float4 a = *(const float4*)(u + 2 * t);
        STEP(a.x, a.y); float p0 = x0, q0 = x2;
        STEP(a.z, a.w);
        *(float4*)(out + 2 * t) = make_float4(p0, q0, x0, x2);
    }
    if (t < te) {
        float2 a = *(const float2*)(u + 2 * t);
        STEP(a.x, a.y);
        *(float2*)(out + 2 * t) = make_float2(x0, x2);
    }
}

extern "C" void kernel_launch(void* const* d_in, const int* in_sizes, int n_in,
                              void* d_out, int out_size) {
    const float* u  = (const float*)d_in[0];
    const float* x0 = (const float*)d_in[1];
    const float* c  = (const float*)d_in[2];
    const float* m  = (const float*)d_in[3];
    const float* k  = (const float*)d_in[4];
    const float* dt = (const float*)d_in[5];
    float* out = (float*)d_out;

    int T = in_sizes[0] / 2;
    int L = (T + P_CHAINS - 1) / P_CHAINS;
    L = (L + 1) & ~1;   // even -> float4 alignment of per-thread u chunks

    k_init<<<1, 16>>>(c, m, k, dt, L);
    k_pass1<<<P_CHAINS / 256, 256>>>(u, T, L);
    k_combine<<<1, CB_THREADS>>>(x0);
    k_pass3<<<P_CHAINS / 256, 256>>>(u, out, T, L);
}

// round 5
// speedup vs baseline: 12.8997x; 2.6432x over previous
#include <cuda_runtime.h>
#include <cuda_bf16.h>

// Blocked-scan RK4 on a 4-state LTI system: x_{t+1} = Phi x_t + Gam u_t (exact algebra).
//   k_init  : 16-thread double build of Phi, Gam, M[s] = Phi^(L*2^s), s=0..17
//   k_pass1 : per-chain affine offsets (chain 0 starts from x0); coalesced g_b
//   k_scan1 : 256 blocks x 1024 thr, per-block Kogge-Stone (constant-matrix trick)
//   k_scan2 : 1 block x 256 thr, KS over block aggregates
//   k_pass3 : prologue computes chain start via binary matrix-power product, then
//             re-runs chain emitting y = (z1, z2) per step.

#define P_CHAINS 262144
#define SCAN_T 1024
#define SCAN_BLOCKS 256      // P_CHAINS / SCAN_T

__device__ float g_fPhi[16];
__device__ float g_fGam[8];
__device__ float g_fM[18][16];        // M[s] = Phi^(L * 2^s)
__device__ float4 g_b[P_CHAINS];
__device__ float4 g_scan[P_CHAINS];   // block-local inclusive scans
__device__ float4 g_agg[SCAN_BLOCKS];
__device__ float4 g_aggs[SCAN_BLOCKS]; // inclusive scan of aggregates

__global__ void k_init(const float* c, const float* m, const float* k,
                       const float* dtp, int L) {
    __shared__ double sA[16], sP[16], sT[16], sR[16], sBs[16];
    int t = threadIdx.x;           // 16 threads
    int r = t >> 2, col = t & 3;

    double c1 = c[0], c2 = c[1], c3 = c[2];
    double m1 = m[0], m2 = m[1];
    double k1 = k[0], k2 = k[1], k3 = k[2];
    double h = dtp[0];

    if (t == 0) {
        sA[0] = 0.0;  sA[1] = 1.0;  sA[2] = 0.0;  sA[3] = 0.0;
        sA[4] = -(k1 + k2) / m1; sA[5] = -(c1 + c2) / m1; sA[6] = k2 / m1; sA[7] = c2 / m1;
        sA[8] = 0.0;  sA[9] = 0.0;  sA[10] = 0.0; sA[11] = 1.0;
        sA[12] = k2 / m2; sA[13] = c2 / m2; sA[14] = -(k3 + k2) / m2; sA[15] = -(c3 + c2) / m2;
    }
    __syncwarp(0xffffu);

    double id = (r == col) ? 1.0 : 0.0;
    double h2 = h * h, h3 = h2 * h, h4 = h3 * h;
    double ph = id + h * sA[t];                 // Phi accumulator
    double g4 = h * id + (h2 / 2.0) * sA[t];    // G4 accumulator
    sP[t] = sA[t];
    __syncwarp(0xffffu);

    double coefP[3] = { h2 / 2.0, h3 / 6.0, h4 / 24.0 };
    double coefG[2] = { h3 / 6.0, h4 / 24.0 };
    for (int q = 0; q < 3; q++) {               // A^2, A^3, A^4
        double s = 0.0;
        for (int kk = 0; kk < 4; kk++) s += sP[r * 4 + kk] * sA[kk * 4 + col];
        __syncwarp(0xffffu);
        sP[t] = s;
        __syncwarp(0xffffu);
        ph += coefP[q] * s;
        if (q < 2) g4 += coefG[q] * s;
    }

    g_fPhi[t] = (float)ph;
    sT[t] = g4;
    __syncwarp(0xffffu);
    if (t < 8) {   // Gam = G4 * B with B[1][0]=1/m1, B[3][1]=1/m2
        int rr = t >> 1, cc = t & 1;
        g_fGam[t] = (float)(sT[rr * 4 + (cc ? 3 : 1)] / (cc ? m2 : m1));
    }

    // sR = Phi^L (binary exponentiation, parallel 4x4 matmuls)
    sR[t] = id;
    sBs[t] = ph;
    __syncwarp(0xffffu);
    int e = L;
    while (e) {
        if (e & 1) {
            double s = 0.0;
            for (int kk = 0; kk < 4; kk++) s += sR[r * 4 + kk] * sBs[kk * 4 + col];
            __syncwarp(0xffffu);
            sR[t] = s;
            __syncwarp(0xffffu);
        }
        e >>= 1;
        if (e) {
            double s = 0.0;
            for (int kk = 0; kk < 4; kk++) s += sBs[r * 4 + kk] * sBs[kk * 4 + col];
            __syncwarp(0xffffu);
            sBs[t] = s;
            __syncwarp(0xffffu);
        }
    }
    g_fM[0][t] = (float)sR[t];
    for (int ms = 1; ms < 18; ms++) {           // successive squarings
        double s = 0.0;
        for (int kk = 0; kk < 4; kk++) s += sR[r * 4 + kk] * sR[kk * 4 + col];
        __syncwarp(0xffffu);
        sR[t] = s;
        __syncwarp(0xffffu);
        g_fM[ms][t] = (float)sR[t];
    }
}

#define STEP(ua, ub)                                                                         \
    do {                                                                                     \
        float n0 = fmaf(P[3],  x3, fmaf(P[2],  x2, fmaf(P[1],  x1, fmaf(P[0],  x0,          \
                   fmaf(G[1], (ub), G[0] * (ua))))));                                        \
        float n1 = fmaf(P[7],  x3, fmaf(P[6],  x2, fmaf(P[5],  x1, fmaf(P[4],  x0,          \
                   fmaf(G[3], (ub), G[2] * (ua))))));                                        \
        float n2 = fmaf(P[11], x3, fmaf(P[10], x2, fmaf(P[9],  x1, fmaf(P[8],  x0,          \
                   fmaf(G[5], (ub), G[4] * (ua))))));                                        \
        float n3 = fmaf(P[15], x3, fmaf(P[14], x2, fmaf(P[13], x1, fmaf(P[12], x0,          \
                   fmaf(G[7], (ub), G[6] * (ua))))));                                        \
        x0 = n0; x1 = n1; x2 = n2; x3 = n3;                                                  \
    } while (0)

// KS affine composition: v = M*w + v
#define KSUP(M, v, w)                                                                        \
    do {                                                                                     \
        float n0 = fmaf(M[0],  w.x, fmaf(M[1],  w.y, fmaf(M[2],  w.z, fmaf(M[3],  w.w, v.x)))); \
        float n1 = fmaf(M[4],  w.x, fmaf(M[5],  w.y, fmaf(M[6],  w.z, fmaf(M[7],  w.w, v.y)))); \
        float n2 = fmaf(M[8],  w.x, fmaf(M[9],  w.y, fmaf(M[10], w.z, fmaf(M[11], w.w, v.z)))); \
        float n3 = fmaf(M[12], w.x, fmaf(M[13], w.y, fmaf(M[14], w.z, fmaf(M[15], w.w, v.w)))); \
        v.x = n0; v.y = n1; v.z = n2; v.w = n3;                                              \
    } while (0)

__global__ void __launch_bounds__(256) k_pass1(const float* __restrict__ u,
                                               const float* __restrict__ x0in,
                                               int T, int L) {
    int p = blockIdx.x * blockDim.x + threadIdx.x;
    float P[16], G[8];
#pragma unroll
    for (int i = 0; i < 16; i++) P[i] = g_fPhi[i];
#pragma unroll
    for (int i = 0; i < 8; i++) G[i] = g_fGam[i];

    float x0 = 0.f, x1 = 0.f, x2 = 0.f, x3 = 0.f;
    if (p == 0) { x0 = x0in[0]; x1 = x0in[1]; x2 = x0in[2]; x3 = x0in[3]; }
    int t0 = p * L;
    int te = t0 + L; if (te > T) te = T;
    int t = t0;
    for (; t + 8 <= te; t += 8) {
        const float4* b4 = (const float4*)(u + 2 * t);
        float4 a0 = b4[0], a1 = b4[1], a2 = b4[2], a3 = b4[3];
        STEP(a0.x, a0.y); STEP(a0.z, a0.w);
        STEP(a1.x, a1.y); STEP(a1.z, a1.w);
        STEP(a2.x, a2.y); STEP(a2.z, a2.w);
        STEP(a3.x, a3.y); STEP(a3.z, a3.w);
    }
    for (; t + 2 <= te; t += 2) {
        float4 a = *(const float4*)(u + 2 * t);
        STEP(a.x, a.y); STEP(a.z, a.w);
    }
    if (t < te) {
        float2 a = *(const float2*)(u + 2 * t);
        STEP(a.x, a.y);
    }
    g_b[p] = make_float4(x0, x1, x2, x3);
}

__global__ void __launch_bounds__(SCAN_T) k_scan1() {
    __shared__ float sM[10][16];
    __shared__ float4 V[SCAN_T];
    int tid = threadIdx.x;
    int q = blockIdx.x * SCAN_T + tid;
    if (tid < 160) ((float*)sM)[tid] = ((const float*)g_fM)[tid];
    float4 v = g_b[q];
    V[tid] = v;
    __syncthreads();
#pragma unroll
    for (int s = 0; s < 10; s++) {
        int d = 1 << s;
        float4 w;
        bool act = (tid >= d);
        if (act) w = V[tid - d];
        __syncthreads();
        if (act) {
            const float* M = sM[s];
            KSUP(M, v, w);
            V[tid] = v;
        }
        __syncthreads();
    }
    g_scan[q] = v;
    if (tid == SCAN_T - 1) g_agg[blockIdx.x] = v;
}

__global__ void __launch_bounds__(SCAN_BLOCKS) k_scan2() {
    __shared__ float sM[8][16];
    __shared__ float4 V[SCAN_BLOCKS];
    int tid = threadIdx.x;
    if (tid < 128) ((float*)sM)[tid] = ((const float*)g_fM)[160 + tid];
    float4 v = g_agg[tid];
    V[tid] = v;
    __syncthreads();
#pragma unroll
    for (int s = 0; s < 8; s++) {
        int d = 1 << s;
        float4 w;
        bool act = (tid >= d);
        if (act) w = V[tid - d];
        __syncthreads();
        if (act) {
            const float* M = sM[s];
            KSUP(M, v, w);
            V[tid] = v;
        }
        __syncthreads();
    }
    g_aggs[tid] = v;
}

__global__ void __launch_bounds__(256) k_pass3(const float* __restrict__ u,
                                               const float* __restrict__ x0in,
                                               float* __restrict__ out, int T, int L) {
    __shared__ float sM[10][16];
    int tid = threadIdx.x;
    int p = blockIdx.x * blockDim.x + tid;
    if (tid < 160) ((float*)sM)[tid] = ((const float*)g_fM)[tid];
    __syncthreads();

    int t0 = p * L;
    if (t0 >= T) return;

    // chain start: x_start[p] = Phi^{iL} * aggs[b-1] + scan[p-1]   (i = p%1024, b = p/1024)
    float x0, x1, x2, x3;
    if (p == 0) {
        x0 = x0in[0]; x1 = x0in[1]; x2 = x0in[2]; x3 = x0in[3];
    } else {
        int i = p & (SCAN_T - 1), b = p >> 10;
        float v0 = 0.f, v1 = 0.f, v2 = 0.f, v3 = 0.f;
        if (b > 0) {
            float4 o = g_aggs[b - 1];
            v0 = o.x; v1 = o.y; v2 = o.z; v3 = o.w;
#pragma unroll
            for (int s = 0; s < 10; s++)
                if ((i >> s) & 1) {
                    const float* M = sM[s];
                    float n0 = fmaf(M[0],  v0, fmaf(M[1],  v1, fmaf(M[2],  v2, M[3]  * v3)));
                    float n1 = fmaf(M[4],  v0, fmaf(M[5],  v1, fmaf(M[6],  v2, M[7]  * v3)));
                    float n2 = fmaf(M[8],  v0, fmaf(M[9],  v1, fmaf(M[10], v2, M[11] * v3)));
                    float n3 = fmaf(M[12], v0, fmaf(M[13], v1, fmaf(M[14], v2, M[15] * v3)));
                    v0 = n0; v1 = n1; v2 = n2; v3 = n3;
                }
        }
        if (i > 0) {
            float4 sc = g_scan[p - 1];
            v0 += sc.x; v1 += sc.y; v2 += sc.z; v3 += sc.w;
        }
        x0 = v0; x1 = v1; x2 = v2; x3 = v3;
    }

    float P[16], G[8];
#pragma unroll
    for (int i = 0; i < 16; i++) P[i] = g_fPhi[i];
#pragma unroll
    for (int i = 0; i < 8; i++) G[i] = g_fGam[i];

    int te = t0 + L; if (te > T) te = T;
    int t = t0;
    for (; t + 8 <= te; t += 8) {
        const float4* b4 = (const float4*)(u + 2 * t);
        float4 a0 = b4[0], a1 = b4[1], a2 = b4[2], a3 = b4[3];
        float4* o4 = (float4*)(out + 2 * t);
        STEP(a0.x, a0.y); float p0 = x0, q0 = x2;
        STEP(a0.z, a0.w); o4[0] = make_float4(p0, q0, x0, x2);
        STEP(a1.x, a1.y); float p1 = x0, q1 = x2;
        STEP(a1.z, a1.w); o4[1] = make_float4(p1, q1, x0, x2);
        STEP(a2.x, a2.y); float p2 = x0, q2 = x2;
        STEP(a2.z, a2.w); o4[2] = make_float4(p2, q2, x0, x2);
        STEP(a3.x, a3.y); float p3 = x0, q3 = x2;
        STEP(a3.z, a3.w); o4[3] = make_float4(p3, q3, x0, x2);
    }
    for (; t + 2 <= te; t += 2) {
        float4 a = *(const float4*)(u + 2 * t);
        STEP(a.x, a.y); float p0 = x0, q0 = x2;
        STEP(a.z, a.w);
        *(float4*)(out + 2 * t) = make_float4(p0, q0, x0, x2);
    }
    if (t < te) {
        float2 a = *(const float2*)(u + 2 * t);
        STEP(a.x, a.y);
        *(float2*)(out + 2 * t) = make_float2(x0, x2);
    }
}

extern "C" void kernel_launch(void* const* d_in, const int* in_sizes, int n_in,
                              void* d_out, int out_size) {
    const float* u  = (const float*)d_in[0];
    const float* x0 = (const float*)d_in[1];
    const float* c  = (const float*)d_in[2];
    const float* m  = (const float*)d_in[3];
    const float* k  = (const float*)d_in[4];
    const float* dt = (const float*)d_in[5];
    float* out = (float*)d_out;

    int T = in_sizes[0] / 2;
    int L = (T + P_CHAINS - 1) / P_CHAINS;
    L = (L + 1) & ~1;   // even -> float4 alignment of per-thread u chunks

    k_init<<<1, 16>>>(c, m, k, dt, L);
    k_pass1<<<P_CHAINS / 256, 256>>>(u, x0, T, L);
    k_scan1<<<SCAN_BLOCKS, SCAN_T>>>();
    k_scan2<<<1, SCAN_BLOCKS>>>();
    k_pass3<<<P_CHAINS / 256, 256>>>(u, x0, out, T, L);
}